// round 9
// baseline (speedup 1.0000x reference)
#include <cuda_runtime.h>
#include <cmath>

#define NMAX 20000

__device__ float g_PHI[NMAX * 32];
__device__ float g_ENV[NMAX];

// ---------------------------------------------------------------------------
// Edge kernel (R4-proven artifact): scatter env-weighted RBF vector + env.
// ---------------------------------------------------------------------------
__global__ void edge_kernel(const float* __restrict__ dist,
                            const int* __restrict__ nb, int E,
                            float mu0, float delta, float inv_delta,
                            float beta, float c2, float q)
{
    int e = blockIdx.x * blockDim.x + threadIdx.x;
    if (e >= E) return;
    float d = dist[e];
    int j = nb[e];
    float env = 0.0f;
    if (d < 5.0f) env = 0.5f * (__cosf(0.62831853071795864769f * d) + 1.0f);
    atomicAdd(&g_ENV[j], env);

    float t = __expf(-d);
    int r0 = (int)floorf((t - mu0) * inv_delta + 0.5f);
    r0 = max(0, min(31, r0));
    float u0 = t - (mu0 + delta * (float)r0);
    float p0 = env * __expf(-beta * u0 * u0);
    float* phr = g_PHI + (size_t)j * 32;
    const float THR = 1e-6f;
    if (p0 > THR) atomicAdd(&phr[r0], p0);

    float w = __expf(c2 * (t - (mu0 + delta * ((float)r0 + 0.5f))));
    float p = p0;
    for (int r = r0 + 1; r < 32; ++r) {
        p *= w; w *= q;
        if (p <= THR) break;
        atomicAdd(&phr[r], p);
    }
    w = __expf(-c2 * (t - (mu0 + delta * ((float)r0 - 0.5f))));
    p = p0;
    for (int r = r0 - 1; r >= 0; --r) {
        p *= w; w *= q;
        if (p <= THR) break;
        atomicAdd(&phr[r], p);
    }
}

// ---------------------------------------------------------------------------
// f32x2 packed FMA helpers
// ---------------------------------------------------------------------------
__device__ __forceinline__ void ffma2(unsigned long long& d,
                                      unsigned long long a,
                                      unsigned long long b)
{
    asm("fma.rn.f32x2 %0, %1, %2, %0;" : "+l"(d) : "l"(a), "l"(b));
}
__device__ __forceinline__ float sum2(unsigned long long v)
{
    float lo, hi;
    asm("mov.b64 {%0, %1}, %2;" : "=f"(lo), "=f"(hi) : "l"(v));
    return lo + hi;
}

__device__ __forceinline__ void decomp9(const float x[9], float* iso,
                                        float a[3], float s[5])
{
    float m = (x[0] + x[4] + x[8]) * (1.0f / 3.0f);
    *iso = m;
    a[0] = 0.5f * (x[1] - x[3]);
    a[1] = 0.5f * (x[2] - x[6]);
    a[2] = 0.5f * (x[5] - x[7]);
    s[0] = x[0] - m;
    s[1] = 0.5f * (x[1] + x[3]);
    s[2] = 0.5f * (x[2] + x[6]);
    s[3] = x[4] - m;
    s[4] = 0.5f * (x[5] + x[7]);
}

__device__ __forceinline__ void build9(float iso, const float a[3],
                                       const float s[5], float Y[9])
{
    Y[0] = iso + s[0];        Y[1] = a[0] + s[1];       Y[2] = a[1] + s[2];
    Y[3] = s[1] - a[0];       Y[4] = iso + s[3];        Y[5] = a[2] + s[4];
    Y[6] = s[2] - a[1];       Y[7] = s[4] - a[2];       Y[8] = iso - s[0] - s[3];
}

// ---------------------------------------------------------------------------
// Node kernel: 10 warps = 5 warp-PAIRS per block; a pair shares 6 nodes.
// Each warp owns 32 output channels (one per lane). 6-node groups amortize
// the 98KB/node-group weight stream (weight slots/node: 192 -> 128) and the
// pair barriers. Reg cap 204 @ 320 threads (est ~195, no spills).
// ---------------------------------------------------------------------------
#define NPAIR 5
#define GRP 6
#define WROW 68
#define PLANE 68
#define CPSZ (9 * PLANE)            // 612 per node
#define OFF_W    0                  // 6 * 64 * 68 = 26112
#define OFF_WDT  26112              // WdT[32][192] = 6144
#define OFF_PAIR 32256
#define PSZ      4448               // cp 6*612=3672 | xs 576 | phi 6*33=198 | pad
#define SMEM_FLOATS (OFF_PAIR + NPAIR * PSZ)   // 54,496 floats = 217,984 B

#define PAIR_BAR() asm volatile("bar.sync %0, 64;" :: "r"(barid) : "memory")

template<int NC>
__device__ __forceinline__ void sector_pass(const float* __restrict__ Wsec,
                                            const float* __restrict__ cp,
                                            int c,
                                            unsigned long long acc[NC][GRP])
{
    const float* w = Wsec + c * WROW;
    #pragma unroll 4
    for (int j = 0; j < 16; ++j) {
        ulonglong2 wv = *(const ulonglong2*)(w + 4 * j);
        #pragma unroll
        for (int n = 0; n < GRP; ++n) {
            const float* base = cp + n * CPSZ + 4 * j;
            #pragma unroll
            for (int k = 0; k < NC; ++k) {
                ulonglong2 m = *(const ulonglong2*)(base + k * PLANE);
                ffma2(acc[k][n], wv.x, m.x);
                ffma2(acc[k][n], wv.y, m.y);
            }
        }
    }
}

__global__ __launch_bounds__(320, 1)
void node_kernel(const float* __restrict__ X,
    const float* __restrict__ WIa, const float* __restrict__ WAa, const float* __restrict__ WSa,
    const float* __restrict__ WIb, const float* __restrict__ WAb, const float* __restrict__ WSb,
    const float* __restrict__ Wd, const float* __restrict__ bd,
    float* __restrict__ out, int N)
{
    extern __shared__ float sm[];
    int tid   = threadIdx.x;
    int warp  = tid >> 5;
    int lane  = tid & 31;
    int pair  = warp >> 1;
    int half  = warp & 1;
    int c     = lane + 32 * half;     // this thread's output channel
    int pid   = tid & 63;             // id within pair
    int barid = pair + 1;             // named barrier per pair (1..5)

    // ---- stage weights (once per block), A,S,I order ----
    {
        const float* Ws[6] = {WAa, WSa, WIa, WAb, WSb, WIb};
        #pragma unroll
        for (int m = 0; m < 6; ++m) {
            const float* src = Ws[m];
            float* dst = sm + OFF_W + m * (64 * WROW);
            for (int idx = tid; idx < 4096; idx += 320)
                dst[(idx >> 6) * WROW + (idx & 63)] = src[idx];
        }
        for (int idx = tid; idx < 6144; idx += 320) {
            int gc = idx >> 5, r = idx & 31;
            sm[OFF_WDT + r * 192 + gc] = Wd[idx];
        }
    }
    float bI = bd[c], bA = bd[64 + c], bS = bd[128 + c];
    __syncthreads();

    float* cp   = sm + OFF_PAIR + pair * PSZ;     // 6 * 612
    float* xs   = cp + GRP * CPSZ;                 // 576
    float* phis = xs + 576;                        // 6 * 33

    const float* smWA_a = sm + OFF_W + 0 * (64 * WROW);
    const float* smWS_a = sm + OFF_W + 1 * (64 * WROW);
    const float* smWI_a = sm + OFF_W + 2 * (64 * WROW);
    const float* smWA_b = sm + OFF_W + 3 * (64 * WROW);
    const float* smWS_b = sm + OFF_W + 4 * (64 * WROW);
    const float* smWI_b = sm + OFF_W + 5 * (64 * WROW);
    const float* smWdT  = sm + OFF_WDT;

    int Q = (N + GRP - 1) / GRP;
    int gp = blockIdx.x * NPAIR + pair;
    int step = gridDim.x * NPAIR;

    for (int q = gp; q < Q; q += step) {
        int n0 = q * GRP;

        // ---- stage phi (each warp stages 3 of the 6 nodes) + env ----
        #pragma unroll
        for (int t = 0; t < 3; ++t) {
            int n = half * 3 + t;
            int node = n0 + n;
            bool v = node < N;
            phis[n * 33 + lane] = v ? g_PHI[(size_t)node * 32 + lane] : 0.0f;
        }
        float env[GRP];
        #pragma unroll
        for (int n = 0; n < GRP; ++n) {
            int node = n0 + n;
            env[n] = (node < N) ? g_ENV[node] : 0.0f;
        }

        // ---- per node: pair-cooperative stage X, decompose own channel ----
        #pragma unroll
        for (int n = 0; n < GRP; ++n) {
            int node = n0 + n;
            if (node < N) {
                const float4* src = (const float4*)(X + (size_t)node * 576);
                float4* dst = (float4*)xs;
                #pragma unroll
                for (int i = 0; i < 3; ++i) {
                    int idx = pid + 64 * i;
                    if (idx < 144) dst[idx] = src[idx];
                }
            }
            PAIR_BAR();
            if (node < N) {
                float x[9];
                #pragma unroll
                for (int k = 0; k < 9; ++k) x[k] = xs[c * 9 + k];
                float f = 0.0f;
                #pragma unroll
                for (int k = 0; k < 9; ++k) f += x[k] * x[k];
                float sc = __fdividef(1.0f, f + 1.0f);
                #pragma unroll
                for (int k = 0; k < 9; ++k) x[k] *= sc;
                float iso, a[3], s[5];
                decomp9(x, &iso, a, s);
                float* cpn = cp + n * CPSZ;
                cpn[0 * PLANE + c] = a[0];
                cpn[1 * PLANE + c] = a[1];
                cpn[2 * PLANE + c] = a[2];
                cpn[3 * PLANE + c] = s[0];
                cpn[4 * PLANE + c] = s[1];
                cpn[5 * PLANE + c] = s[2];
                cpn[6 * PLANE + c] = s[3];
                cpn[7 * PLANE + c] = s[4];
                cpn[8 * PLANE + c] = iso;
            }
            PAIR_BAR();
        }

        // ---- coefficient GEMV (one channel per thread, 6 nodes) ----
        float fI[GRP], fA[GRP], fS[GRP];
        #pragma unroll
        for (int n = 0; n < GRP; ++n) {
            fI[n] = env[n] * bI;
            fA[n] = env[n] * bA;
            fS[n] = env[n] * bS;
        }
        #pragma unroll 4
        for (int r = 0; r < 32; ++r) {
            const float* wr = smWdT + r * 192;
            float wi = wr[c], wa = wr[64 + c], ws = wr[128 + c];
            #pragma unroll
            for (int n = 0; n < GRP; ++n) {
                float p = phis[n * 33 + r];
                fI[n] += wi * p;
                fA[n] += wa * p;
                fS[n] += ws * p;
            }
        }

        // ---- pre mixes (sector-split; 32 out-channels per warp) ----
        float yi[GRP], ya[3][GRP], ys[5][GRP];
        {
            unsigned long long accA[3][GRP] = {};
            sector_pass<3>(smWA_a, cp, c, accA);
            #pragma unroll
            for (int k = 0; k < 3; ++k)
                #pragma unroll
                for (int n = 0; n < GRP; ++n) ya[k][n] = sum2(accA[k][n]);
        }
        {
            unsigned long long accS[5][GRP] = {};
            sector_pass<5>(smWS_a, cp + 3 * PLANE, c, accS);
            #pragma unroll
            for (int k = 0; k < 5; ++k)
                #pragma unroll
                for (int n = 0; n < GRP; ++n) ys[k][n] = sum2(accS[k][n]);
        }
        {
            unsigned long long accI[1][GRP] = {};
            sector_pass<1>(smWI_a, cp + 8 * PLANE, c, accI);
            #pragma unroll
            for (int n = 0; n < GRP; ++n) yi[n] = sum2(accI[0][n]);
        }
        PAIR_BAR();   // everyone done reading comps before sandwich overwrite

        // ---- sandwich: Z = YM + MY, normalize, decompose -> overwrite comps
        #pragma unroll
        for (int n = 0; n < GRP; ++n) {
            float* cpn = cp + n * CPSZ;
            float Y[9], M[9];
            float av[3] = {ya[0][n], ya[1][n], ya[2][n]};
            float sv[5] = {ys[0][n], ys[1][n], ys[2][n], ys[3][n], ys[4][n]};
            build9(yi[n], av, sv, Y);
            float mi = fI[n] * cpn[8 * PLANE + c];
            float A[3] = {fA[n] * cpn[0 * PLANE + c],
                          fA[n] * cpn[1 * PLANE + c],
                          fA[n] * cpn[2 * PLANE + c]};
            float S[5] = {fS[n] * cpn[3 * PLANE + c],
                          fS[n] * cpn[4 * PLANE + c],
                          fS[n] * cpn[5 * PLANE + c],
                          fS[n] * cpn[6 * PLANE + c],
                          fS[n] * cpn[7 * PLANE + c]};
            build9(mi, A, S, M);
            float Z[9];
            #pragma unroll
            for (int i = 0; i < 3; ++i)
                #pragma unroll
                for (int jj = 0; jj < 3; ++jj) {
                    float acc = 0.0f;
                    #pragma unroll
                    for (int k = 0; k < 3; ++k)
                        acc += Y[i * 3 + k] * M[k * 3 + jj]
                             + M[i * 3 + k] * Y[k * 3 + jj];
                    Z[i * 3 + jj] = acc;
                }
            float nrm = 0.0f;
            #pragma unroll
            for (int k = 0; k < 9; ++k) { float v = Z[k] + 1.0f; nrm += v * v; }
            float inv = __fdividef(1.0f, nrm);
            #pragma unroll
            for (int k = 0; k < 9; ++k) Z[k] *= inv;
            float iso, a2[3], s2[5];
            decomp9(Z, &iso, a2, s2);
            cpn[0 * PLANE + c] = a2[0];
            cpn[1 * PLANE + c] = a2[1];
            cpn[2 * PLANE + c] = a2[2];
            cpn[3 * PLANE + c] = s2[0];
            cpn[4 * PLANE + c] = s2[1];
            cpn[5 * PLANE + c] = s2[2];
            cpn[6 * PLANE + c] = s2[3];
            cpn[7 * PLANE + c] = s2[4];
            cpn[8 * PLANE + c] = iso;
        }
        PAIR_BAR();   // sandwich writes visible before post mixes

        // ---- post mixes ----
        {
            unsigned long long accA[3][GRP] = {};
            sector_pass<3>(smWA_b, cp, c, accA);
            #pragma unroll
            for (int k = 0; k < 3; ++k)
                #pragma unroll
                for (int n = 0; n < GRP; ++n) ya[k][n] = sum2(accA[k][n]);
        }
        {
            unsigned long long accS[5][GRP] = {};
            sector_pass<5>(smWS_b, cp + 3 * PLANE, c, accS);
            #pragma unroll
            for (int k = 0; k < 5; ++k)
                #pragma unroll
                for (int n = 0; n < GRP; ++n) ys[k][n] = sum2(accS[k][n]);
        }
        {
            unsigned long long accI[1][GRP] = {};
            sector_pass<1>(smWI_b, cp + 8 * PLANE, c, accI);
            #pragma unroll
            for (int n = 0; n < GRP; ++n) yi[n] = sum2(accI[0][n]);
        }

        // ---- output: O = Y2 + Y2@Y2, stage per node, pair-coalesced store --
        #pragma unroll
        for (int n = 0; n < GRP; ++n) {
            int node = n0 + n;
            {
                float av[3] = {ya[0][n], ya[1][n], ya[2][n]};
                float sv[5] = {ys[0][n], ys[1][n], ys[2][n], ys[3][n], ys[4][n]};
                float Y2[9];
                build9(yi[n], av, sv, Y2);
                float* od = xs + c * 9;
                #pragma unroll
                for (int i = 0; i < 3; ++i)
                    #pragma unroll
                    for (int jj = 0; jj < 3; ++jj) {
                        float acc = Y2[i * 3 + jj];
                        #pragma unroll
                        for (int k = 0; k < 3; ++k)
                            acc += Y2[i * 3 + k] * Y2[k * 3 + jj];
                        od[i * 3 + jj] = acc;
                    }
            }
            PAIR_BAR();
            if (node < N) {
                float4* dst = (float4*)(out + (size_t)node * 576);
                const float4* src = (const float4*)xs;
                #pragma unroll
                for (int i = 0; i < 3; ++i) {
                    int idx = pid + 64 * i;
                    if (idx < 144) dst[idx] = src[idx];
                }
            }
            PAIR_BAR();
        }
    }
}

// ---------------------------------------------------------------------------
extern "C" void kernel_launch(void* const* d_in, const int* in_sizes, int n_in,
                              void* d_out, int out_size)
{
    const float* X    = (const float*)d_in[0];
    const float* dist = (const float*)d_in[1];
    const int*   nb   = (const int*)d_in[2];
    const float* WIa  = (const float*)d_in[3];
    const float* WAa  = (const float*)d_in[4];
    const float* WSa  = (const float*)d_in[5];
    const float* WIb  = (const float*)d_in[6];
    const float* WAb  = (const float*)d_in[7];
    const float* WSb  = (const float*)d_in[8];
    const float* Wd   = (const float*)d_in[9];
    const float* bd   = (const float*)d_in[10];
    float* out = (float*)d_out;

    int N = in_sizes[0] / 576;
    int E = in_sizes[1];

    void* phi_ptr = nullptr;
    void* env_ptr = nullptr;
    cudaGetSymbolAddress(&phi_ptr, g_PHI);
    cudaGetSymbolAddress(&env_ptr, g_ENV);
    cudaMemsetAsync(phi_ptr, 0, sizeof(float) * (size_t)N * 32, 0);
    cudaMemsetAsync(env_ptr, 0, sizeof(float) * (size_t)N, 0);

    double e5    = exp(-5.0);
    double delta = (1.0 - e5) / 31.0;
    double bb    = (2.0 / 32.0) * (1.0 - e5);
    double beta  = 1.0 / (bb * bb);
    float  c2    = (float)(2.0 * beta * delta);
    float  qf    = (float)exp(-2.0 * beta * delta * delta);

    edge_kernel<<<(E + 255) / 256, 256>>>(dist, nb, E,
        (float)e5, (float)delta, (float)(1.0 / delta), (float)beta, c2, qf);

    static int smem_set = 0;
    if (!smem_set) {
        cudaFuncSetAttribute(node_kernel,
                             cudaFuncAttributeMaxDynamicSharedMemorySize,
                             SMEM_FLOATS * sizeof(float));
        smem_set = 1;
    }
    node_kernel<<<148, 320, SMEM_FLOATS * sizeof(float)>>>(
        X, WIa, WAa, WSa, WIb, WAb, WSb, Wd, bd, out, N);
}

// round 10
// speedup vs baseline: 1.1084x; 1.1084x over previous
#include <cuda_runtime.h>
#include <cmath>

#define NMAX 20000

__device__ float g_PHI[NMAX * 32];
__device__ float g_ENV[NMAX];

// ---------------------------------------------------------------------------
// Edge kernel (R4-proven artifact): scatter env-weighted RBF vector + env.
// ---------------------------------------------------------------------------
__global__ void edge_kernel(const float* __restrict__ dist,
                            const int* __restrict__ nb, int E,
                            float mu0, float delta, float inv_delta,
                            float beta, float c2, float q)
{
    int e = blockIdx.x * blockDim.x + threadIdx.x;
    if (e >= E) return;
    float d = dist[e];
    int j = nb[e];
    float env = 0.0f;
    if (d < 5.0f) env = 0.5f * (__cosf(0.62831853071795864769f * d) + 1.0f);
    atomicAdd(&g_ENV[j], env);

    float t = __expf(-d);
    int r0 = (int)floorf((t - mu0) * inv_delta + 0.5f);
    r0 = max(0, min(31, r0));
    float u0 = t - (mu0 + delta * (float)r0);
    float p0 = env * __expf(-beta * u0 * u0);
    float* phr = g_PHI + (size_t)j * 32;
    const float THR = 1e-6f;
    if (p0 > THR) atomicAdd(&phr[r0], p0);

    float w = __expf(c2 * (t - (mu0 + delta * ((float)r0 + 0.5f))));
    float p = p0;
    for (int r = r0 + 1; r < 32; ++r) {
        p *= w; w *= q;
        if (p <= THR) break;
        atomicAdd(&phr[r], p);
    }
    w = __expf(-c2 * (t - (mu0 + delta * ((float)r0 - 0.5f))));
    p = p0;
    for (int r = r0 - 1; r >= 0; --r) {
        p *= w; w *= q;
        if (p <= THR) break;
        atomicAdd(&phr[r], p);
    }
}

// ---------------------------------------------------------------------------
// f32x2 packed FMA helpers
// ---------------------------------------------------------------------------
__device__ __forceinline__ void ffma2(unsigned long long& d,
                                      unsigned long long a,
                                      unsigned long long b)
{
    asm("fma.rn.f32x2 %0, %1, %2, %0;" : "+l"(d) : "l"(a), "l"(b));
}
__device__ __forceinline__ float sum2(unsigned long long v)
{
    float lo, hi;
    asm("mov.b64 {%0, %1}, %2;" : "=f"(lo), "=f"(hi) : "l"(v));
    return lo + hi;
}

__device__ __forceinline__ void decomp9(const float x[9], float* iso,
                                        float a[3], float s[5])
{
    float m = (x[0] + x[4] + x[8]) * (1.0f / 3.0f);
    *iso = m;
    a[0] = 0.5f * (x[1] - x[3]);
    a[1] = 0.5f * (x[2] - x[6]);
    a[2] = 0.5f * (x[5] - x[7]);
    s[0] = x[0] - m;
    s[1] = 0.5f * (x[1] + x[3]);
    s[2] = 0.5f * (x[2] + x[6]);
    s[3] = x[4] - m;
    s[4] = 0.5f * (x[5] + x[7]);
}

__device__ __forceinline__ void build9(float iso, const float a[3],
                                       const float s[5], float Y[9])
{
    Y[0] = iso + s[0];        Y[1] = a[0] + s[1];       Y[2] = a[1] + s[2];
    Y[3] = s[1] - a[0];       Y[4] = iso + s[3];        Y[5] = a[2] + s[4];
    Y[6] = s[2] - a[1];       Y[7] = s[4] - a[2];       Y[8] = iso - s[0] - s[3];
}

// ---------------------------------------------------------------------------
// Node kernel: 16 warps = 8 warp-PAIRS per block; a pair shares 2 nodes.
// Each warp owns 32 output channels (one per lane). 512 threads => 128-reg
// cap; GRP=2 keeps peak live registers ~115 (no spill, unlike R5's h-split).
// occ target 25% (16 warps/SM). env folded into phi smem; GEMV after pre-mix.
// ---------------------------------------------------------------------------
#define NPAIR 8
#define GRP 2
#define WROW 68
#define PLANE 68
#define CPSZ (9 * PLANE)            // 612 per node
#define OFF_W    0                  // 6 * 64 * 68 = 26112
#define OFF_WDT  26112              // WdT[32][192] = 6144
#define OFF_PAIR 32256
#define PSZ      1872               // cp 2*612=1224 | xs 576 | phi 2*33=66 | pad
#define SMEM_FLOATS (OFF_PAIR + NPAIR * PSZ)   // 47,232 floats = 188,928 B

#define PAIR_BAR() asm volatile("bar.sync %0, 64;" :: "r"(barid) : "memory")

template<int NC>
__device__ __forceinline__ void sector_pass(const float* __restrict__ Wsec,
                                            const float* __restrict__ cp,
                                            int c,
                                            unsigned long long acc[NC][GRP])
{
    const float* w = Wsec + c * WROW;
    #pragma unroll 4
    for (int j = 0; j < 16; ++j) {
        ulonglong2 wv = *(const ulonglong2*)(w + 4 * j);
        #pragma unroll
        for (int n = 0; n < GRP; ++n) {
            const float* base = cp + n * CPSZ + 4 * j;
            #pragma unroll
            for (int k = 0; k < NC; ++k) {
                ulonglong2 m = *(const ulonglong2*)(base + k * PLANE);
                ffma2(acc[k][n], wv.x, m.x);
                ffma2(acc[k][n], wv.y, m.y);
            }
        }
    }
}

__global__ __launch_bounds__(512, 1)
void node_kernel(const float* __restrict__ X,
    const float* __restrict__ WIa, const float* __restrict__ WAa, const float* __restrict__ WSa,
    const float* __restrict__ WIb, const float* __restrict__ WAb, const float* __restrict__ WSb,
    const float* __restrict__ Wd, const float* __restrict__ bd,
    float* __restrict__ out, int N)
{
    extern __shared__ float sm[];
    int tid   = threadIdx.x;
    int warp  = tid >> 5;
    int lane  = tid & 31;
    int pair  = warp >> 1;
    int half  = warp & 1;
    int c     = lane + 32 * half;     // this thread's output channel
    int pid   = tid & 63;             // id within pair
    int barid = pair + 1;             // named barrier per pair (1..8)

    // ---- stage weights (once per block), A,S,I order ----
    {
        const float* Ws[6] = {WAa, WSa, WIa, WAb, WSb, WIb};
        #pragma unroll
        for (int m = 0; m < 6; ++m) {
            const float* src = Ws[m];
            float* dst = sm + OFF_W + m * (64 * WROW);
            for (int idx = tid; idx < 4096; idx += 512)
                dst[(idx >> 6) * WROW + (idx & 63)] = src[idx];
        }
        for (int idx = tid; idx < 6144; idx += 512) {
            int gc = idx >> 5, r = idx & 31;
            sm[OFF_WDT + r * 192 + gc] = Wd[idx];
        }
    }
    __syncthreads();

    float* cp   = sm + OFF_PAIR + pair * PSZ;     // 2 * 612
    float* xs   = cp + GRP * CPSZ;                 // 576
    float* phis = xs + 576;                        // 2 * 33 (slot 32 = env)

    const float* smWA_a = sm + OFF_W + 0 * (64 * WROW);
    const float* smWS_a = sm + OFF_W + 1 * (64 * WROW);
    const float* smWI_a = sm + OFF_W + 2 * (64 * WROW);
    const float* smWA_b = sm + OFF_W + 3 * (64 * WROW);
    const float* smWS_b = sm + OFF_W + 4 * (64 * WROW);
    const float* smWI_b = sm + OFF_W + 5 * (64 * WROW);
    const float* smWdT  = sm + OFF_WDT;

    int Q = (N + GRP - 1) / GRP;
    int gp = blockIdx.x * NPAIR + pair;
    int step = gridDim.x * NPAIR;

    for (int q = gp; q < Q; q += step) {
        int n0 = q * GRP;

        // ---- stage phi + env (warp `half` stages node `half`) ----
        {
            int n = half;
            int node = n0 + n;
            bool v = node < N;
            phis[n * 33 + lane] = v ? g_PHI[(size_t)node * 32 + lane] : 0.0f;
            if (lane == 0) phis[n * 33 + 32] = v ? g_ENV[node] : 0.0f;
        }

        // ---- per node: pair-cooperative stage X, decompose own channel ----
        #pragma unroll
        for (int n = 0; n < GRP; ++n) {
            int node = n0 + n;
            if (node < N) {
                const float4* src = (const float4*)(X + (size_t)node * 576);
                float4* dst = (float4*)xs;
                #pragma unroll
                for (int i = 0; i < 3; ++i) {
                    int idx = pid + 64 * i;
                    if (idx < 144) dst[idx] = src[idx];
                }
            }
            PAIR_BAR();
            if (node < N) {
                float x[9];
                #pragma unroll
                for (int k = 0; k < 9; ++k) x[k] = xs[c * 9 + k];
                float f = 0.0f;
                #pragma unroll
                for (int k = 0; k < 9; ++k) f += x[k] * x[k];
                float sc = __fdividef(1.0f, f + 1.0f);
                #pragma unroll
                for (int k = 0; k < 9; ++k) x[k] *= sc;
                float iso, a[3], s[5];
                decomp9(x, &iso, a, s);
                float* cpn = cp + n * CPSZ;
                cpn[0 * PLANE + c] = a[0];
                cpn[1 * PLANE + c] = a[1];
                cpn[2 * PLANE + c] = a[2];
                cpn[3 * PLANE + c] = s[0];
                cpn[4 * PLANE + c] = s[1];
                cpn[5 * PLANE + c] = s[2];
                cpn[6 * PLANE + c] = s[3];
                cpn[7 * PLANE + c] = s[4];
                cpn[8 * PLANE + c] = iso;
            }
            PAIR_BAR();
        }

        // ---- pre mixes (sector-split; 32 out-channels per warp) ----
        float yi[GRP], ya[3][GRP], ys[5][GRP];
        {
            unsigned long long accA[3][GRP] = {};
            sector_pass<3>(smWA_a, cp, c, accA);
            #pragma unroll
            for (int k = 0; k < 3; ++k)
                #pragma unroll
                for (int n = 0; n < GRP; ++n) ya[k][n] = sum2(accA[k][n]);
        }
        {
            unsigned long long accS[5][GRP] = {};
            sector_pass<5>(smWS_a, cp + 3 * PLANE, c, accS);
            #pragma unroll
            for (int k = 0; k < 5; ++k)
                #pragma unroll
                for (int n = 0; n < GRP; ++n) ys[k][n] = sum2(accS[k][n]);
        }
        {
            unsigned long long accI[1][GRP] = {};
            sector_pass<1>(smWI_a, cp + 8 * PLANE, c, accI);
            #pragma unroll
            for (int n = 0; n < GRP; ++n) yi[n] = sum2(accI[0][n]);
        }

        // ---- coefficient GEMV (late: short live range for fI/fA/fS) ----
        float fI[GRP], fA[GRP], fS[GRP];
        #pragma unroll
        for (int n = 0; n < GRP; ++n) {
            float env = phis[n * 33 + 32];
            fI[n] = env * bd[c];
            fA[n] = env * bd[64 + c];
            fS[n] = env * bd[128 + c];
        }
        #pragma unroll 4
        for (int r = 0; r < 32; ++r) {
            const float* wr = smWdT + r * 192;
            float wi = wr[c], wa = wr[64 + c], ws = wr[128 + c];
            #pragma unroll
            for (int n = 0; n < GRP; ++n) {
                float p = phis[n * 33 + r];
                fI[n] += wi * p;
                fA[n] += wa * p;
                fS[n] += ws * p;
            }
        }
        PAIR_BAR();   // everyone done reading comps before sandwich overwrite

        // ---- sandwich: Z = YM + MY, normalize, decompose -> overwrite comps
        #pragma unroll
        for (int n = 0; n < GRP; ++n) {
            float* cpn = cp + n * CPSZ;
            float Y[9], M[9];
            float av[3] = {ya[0][n], ya[1][n], ya[2][n]};
            float sv[5] = {ys[0][n], ys[1][n], ys[2][n], ys[3][n], ys[4][n]};
            build9(yi[n], av, sv, Y);
            float mi = fI[n] * cpn[8 * PLANE + c];
            float A[3] = {fA[n] * cpn[0 * PLANE + c],
                          fA[n] * cpn[1 * PLANE + c],
                          fA[n] * cpn[2 * PLANE + c]};
            float S[5] = {fS[n] * cpn[3 * PLANE + c],
                          fS[n] * cpn[4 * PLANE + c],
                          fS[n] * cpn[5 * PLANE + c],
                          fS[n] * cpn[6 * PLANE + c],
                          fS[n] * cpn[7 * PLANE + c]};
            build9(mi, A, S, M);
            float Z[9];
            #pragma unroll
            for (int i = 0; i < 3; ++i)
                #pragma unroll
                for (int jj = 0; jj < 3; ++jj) {
                    float acc = 0.0f;
                    #pragma unroll
                    for (int k = 0; k < 3; ++k)
                        acc += Y[i * 3 + k] * M[k * 3 + jj]
                             + M[i * 3 + k] * Y[k * 3 + jj];
                    Z[i * 3 + jj] = acc;
                }
            float nrm = 0.0f;
            #pragma unroll
            for (int k = 0; k < 9; ++k) { float v = Z[k] + 1.0f; nrm += v * v; }
            float inv = __fdividef(1.0f, nrm);
            #pragma unroll
            for (int k = 0; k < 9; ++k) Z[k] *= inv;
            float iso, a2[3], s2[5];
            decomp9(Z, &iso, a2, s2);
            cpn[0 * PLANE + c] = a2[0];
            cpn[1 * PLANE + c] = a2[1];
            cpn[2 * PLANE + c] = a2[2];
            cpn[3 * PLANE + c] = s2[0];
            cpn[4 * PLANE + c] = s2[1];
            cpn[5 * PLANE + c] = s2[2];
            cpn[6 * PLANE + c] = s2[3];
            cpn[7 * PLANE + c] = s2[4];
            cpn[8 * PLANE + c] = iso;
        }
        PAIR_BAR();   // sandwich writes visible before post mixes

        // ---- post mixes ----
        {
            unsigned long long accA[3][GRP] = {};
            sector_pass<3>(smWA_b, cp, c, accA);
            #pragma unroll
            for (int k = 0; k < 3; ++k)
                #pragma unroll
                for (int n = 0; n < GRP; ++n) ya[k][n] = sum2(accA[k][n]);
        }
        {
            unsigned long long accS[5][GRP] = {};
            sector_pass<5>(smWS_b, cp + 3 * PLANE, c, accS);
            #pragma unroll
            for (int k = 0; k < 5; ++k)
                #pragma unroll
                for (int n = 0; n < GRP; ++n) ys[k][n] = sum2(accS[k][n]);
        }
        {
            unsigned long long accI[1][GRP] = {};
            sector_pass<1>(smWI_b, cp + 8 * PLANE, c, accI);
            #pragma unroll
            for (int n = 0; n < GRP; ++n) yi[n] = sum2(accI[0][n]);
        }

        // ---- output: O = Y2 + Y2@Y2, stage per node, pair-coalesced store --
        #pragma unroll
        for (int n = 0; n < GRP; ++n) {
            int node = n0 + n;
            {
                float av[3] = {ya[0][n], ya[1][n], ya[2][n]};
                float sv[5] = {ys[0][n], ys[1][n], ys[2][n], ys[3][n], ys[4][n]};
                float Y2[9];
                build9(yi[n], av, sv, Y2);
                float* od = xs + c * 9;
                #pragma unroll
                for (int i = 0; i < 3; ++i)
                    #pragma unroll
                    for (int jj = 0; jj < 3; ++jj) {
                        float acc = Y2[i * 3 + jj];
                        #pragma unroll
                        for (int k = 0; k < 3; ++k)
                            acc += Y2[i * 3 + k] * Y2[k * 3 + jj];
                        od[i * 3 + jj] = acc;
                    }
            }
            PAIR_BAR();
            if (node < N) {
                float4* dst = (float4*)(out + (size_t)node * 576);
                const float4* src = (const float4*)xs;
                #pragma unroll
                for (int i = 0; i < 3; ++i) {
                    int idx = pid + 64 * i;
                    if (idx < 144) dst[idx] = src[idx];
                }
            }
            PAIR_BAR();
        }
    }
}

// ---------------------------------------------------------------------------
extern "C" void kernel_launch(void* const* d_in, const int* in_sizes, int n_in,
                              void* d_out, int out_size)
{
    const float* X    = (const float*)d_in[0];
    const float* dist = (const float*)d_in[1];
    const int*   nb   = (const int*)d_in[2];
    const float* WIa  = (const float*)d_in[3];
    const float* WAa  = (const float*)d_in[4];
    const float* WSa  = (const float*)d_in[5];
    const float* WIb  = (const float*)d_in[6];
    const float* WAb  = (const float*)d_in[7];
    const float* WSb  = (const float*)d_in[8];
    const float* Wd   = (const float*)d_in[9];
    const float* bd   = (const float*)d_in[10];
    float* out = (float*)d_out;

    int N = in_sizes[0] / 576;
    int E = in_sizes[1];

    void* phi_ptr = nullptr;
    void* env_ptr = nullptr;
    cudaGetSymbolAddress(&phi_ptr, g_PHI);
    cudaGetSymbolAddress(&env_ptr, g_ENV);
    cudaMemsetAsync(phi_ptr, 0, sizeof(float) * (size_t)N * 32, 0);
    cudaMemsetAsync(env_ptr, 0, sizeof(float) * (size_t)N, 0);

    double e5    = exp(-5.0);
    double delta = (1.0 - e5) / 31.0;
    double bb    = (2.0 / 32.0) * (1.0 - e5);
    double beta  = 1.0 / (bb * bb);
    float  c2    = (float)(2.0 * beta * delta);
    float  qf    = (float)exp(-2.0 * beta * delta * delta);

    edge_kernel<<<(E + 255) / 256, 256>>>(dist, nb, E,
        (float)e5, (float)delta, (float)(1.0 / delta), (float)beta, c2, qf);

    static int smem_set = 0;
    if (!smem_set) {
        cudaFuncSetAttribute(node_kernel,
                             cudaFuncAttributeMaxDynamicSharedMemorySize,
                             SMEM_FLOATS * sizeof(float));
        smem_set = 1;
    }
    node_kernel<<<148, 512, SMEM_FLOATS * sizeof(float)>>>(
        X, WIa, WAa, WSa, WIb, WAb, WSb, Wd, bd, out, N);
}